// round 3
// baseline (speedup 1.0000x reference)
#include <cuda_runtime.h>

#define BB 16
#define SS 4096
#define DD 1024
#define ROWS_PER_BLOCK 64
#define THREADS 256
#define WARPS (THREADS / 32)

__global__ void zero_out_kernel(float* __restrict__ out) {
    if (threadIdx.x < BB) out[threadIdx.x] = 0.0f;
}

__global__ __launch_bounds__(THREADS, 2)
void ic_reward_kernel(const float* __restrict__ x,
                      const float* __restrict__ W,
                      const float* __restrict__ b,
                      const int* __restrict__ lengths,
                      float* __restrict__ out) {
    const int batch = blockIdx.y;
    const int len = lengths[batch];
    const int row0 = blockIdx.x * ROWS_PER_BLOCK;
    if (row0 >= len) return;  // fully-masked chunk: zero DRAM traffic for x

    const int warp = threadIdx.x >> 5;
    const int lane = threadIdx.x & 31;

    // W hoisted to registers: each lane's slice is row-invariant (64 regs).
    float4 w0r[8], w1r[8];
    #pragma unroll
    for (int k = 0; k < 8; k++) {
        const int idx = k * 32 + lane;
        w0r[k] = reinterpret_cast<const float4*>(W)[idx];
        w1r[k] = reinterpret_cast<const float4*>(W + DD)[idx];
    }

    const float b0 = b[0];
    const float b1 = b[1];

    __shared__ float warp_sums[WARPS];

    const int row_end = min(row0 + ROWS_PER_BLOCK, len);
    const float* xbase = x + (size_t)batch * SS * DD;

    float acc = 0.0f;

    // Each warp owns 8 rows of the 64-row chunk; process 2 per iteration so
    // the 16 LDG.128s of both rows issue before either reduction chain starts.
    for (int row = row0 + warp; row < row_end; row += 2 * WARPS) {
        const int rowB = row + WARPS;
        const bool hasB = (rowB < row_end);

        const float4* xrA = reinterpret_cast<const float4*>(xbase + (size_t)row  * DD);
        const float4* xrB = reinterpret_cast<const float4*>(xbase + (size_t)(hasB ? rowB : row) * DD);

        float a0 = 0.0f, a1 = 0.0f;  // row A partial dots
        float c0 = 0.0f, c1 = 0.0f;  // row B partial dots
        #pragma unroll
        for (int k = 0; k < 8; k++) {
            const int idx = k * 32 + lane;       // coalesced LDG.128
            const float4 xa = xrA[idx];
            const float4 xb = xrB[idx];
            a0 += xa.x * w0r[k].x + xa.y * w0r[k].y + xa.z * w0r[k].z + xa.w * w0r[k].w;
            a1 += xa.x * w1r[k].x + xa.y * w1r[k].y + xa.z * w1r[k].z + xa.w * w1r[k].w;
            c0 += xb.x * w0r[k].x + xb.y * w0r[k].y + xb.z * w0r[k].z + xb.w * w0r[k].w;
            c1 += xb.x * w1r[k].x + xb.y * w1r[k].y + xb.z * w1r[k].z + xb.w * w1r[k].w;
        }

        // Two interleaved warp tree reductions — shuffle chains pipeline.
        #pragma unroll
        for (int o = 16; o > 0; o >>= 1) {
            a0 += __shfl_xor_sync(0xFFFFFFFFu, a0, o);
            a1 += __shfl_xor_sync(0xFFFFFFFFu, a1, o);
            c0 += __shfl_xor_sync(0xFFFFFFFFu, c0, o);
            c1 += __shfl_xor_sync(0xFFFFFFFFu, c1, o);
        }

        if (lane == 0) {
            const float gateA = 1.0f / (1.0f + __expf(-(a0 + b0)));
            acc += gateA * (a1 + b1);
            if (hasB) {
                const float gateB = 1.0f / (1.0f + __expf(-(c0 + b0)));
                acc += gateB * (c1 + b1);
            }
        }
    }

    if (lane == 0) warp_sums[warp] = acc;
    __syncthreads();

    if (threadIdx.x == 0) {
        float total = 0.0f;
        #pragma unroll
        for (int w = 0; w < WARPS; w++) total += warp_sums[w];
        atomicAdd(&out[batch], total);
    }
}

extern "C" void kernel_launch(void* const* d_in, const int* in_sizes, int n_in,
                              void* d_out, int out_size) {
    const float* x       = (const float*)d_in[0];
    const float* W       = (const float*)d_in[1];
    const float* b       = (const float*)d_in[2];
    const int*   lengths = (const int*)d_in[3];
    float* out = (float*)d_out;

    zero_out_kernel<<<1, 32>>>(out);

    dim3 grid(SS / ROWS_PER_BLOCK, BB);  // (64, 16)
    ic_reward_kernel<<<grid, THREADS>>>(x, W, b, lengths, out);
}